// round 9
// baseline (speedup 1.0000x reference)
#include <cuda_runtime.h>
#include <cuda_fp16.h>

#define PATCH_NUM 16
#define RPE_NUM   33          // 2*PATCH_NUM + 1
#define NUM_HEADS 8
#define GH        48
#define GW        48
#define NPIX      2304        // 48*48
#define NB        2
#define TAB_ROWS  (3 * RPE_NUM)   // 99
#define NI        2               // query pixels per block
#define NCOPY     16              // smem replication copies

// ---------------------------------------------------------------------------
// Single fused kernel: one block per (i-pair, b). 576 threads x 4 j each.
//
// Each block REDUNDANTLY computes its image's depth min/max (2304 floats,
// L2-resident) with 1 LDG.128/thread + shfl/smem reduce — removes the
// separate normalization kernel and its launch serialization.
//
// Table in smem as fp16: row-half = 8B (LDS.64), replicated 16x with 128B
// row stride; copy = tid & 15 -> every gather (incl. data-dependent z) is
// bank-conflict-free. fp32 adds in reference association order.
// ---------------------------------------------------------------------------
__global__ __launch_bounds__(576, 2) void rpe_kernel(
    const float* __restrict__ depth,
    const float4* __restrict__ table4, float* __restrict__ out)
{
    __shared__ __align__(128) uint2 s_tab[2][TAB_ROWS][NCOPY];  // 25344 B
    __shared__ float s_mn[18], s_mx[18];
    __shared__ float s_stat[2];                                  // mn, denom

    const int tid = threadIdx.x;
    const int i0  = blockIdx.x * NI;         // first query pixel of this block
    const int b   = blockIdx.y;              // batch
    const int j0  = tid * 4;                 // 576*4 == 2304 == NPIX

    // ---- load this thread's depth quad (also the reduction partition) ----
    const float4 d4 = *reinterpret_cast<const float4*>(&depth[b * NPIX + j0]);

    // ---- table prologue: fp16-convert + replicate ----
    for (int e = tid; e < 2 * TAB_ROWS; e += 576) {
        const int half = (e >= TAB_ROWS) ? 1 : 0;
        const int row  = e - half * TAB_ROWS;
        const float4 f = __ldg(&table4[row * 2 + half]);
        const __half2 a  = __floats2half2_rn(f.x, f.y);
        const __half2 bb = __floats2half2_rn(f.z, f.w);
        uint2 p;
        p.x = *reinterpret_cast<const unsigned int*>(&a);
        p.y = *reinterpret_cast<const unsigned int*>(&bb);
#pragma unroll
        for (int cpw = 0; cpw < NCOPY; ++cpw) s_tab[half][row][cpw] = p;
    }

    // ---- block-wide min/max over the image ----
    float mn = fminf(fminf(d4.x, d4.y), fminf(d4.z, d4.w));
    float mx = fmaxf(fmaxf(d4.x, d4.y), fmaxf(d4.z, d4.w));
#pragma unroll
    for (int o = 16; o > 0; o >>= 1) {
        mn = fminf(mn, __shfl_xor_sync(0xffffffffu, mn, o));
        mx = fmaxf(mx, __shfl_xor_sync(0xffffffffu, mx, o));
    }
    if ((tid & 31) == 0) { s_mn[tid >> 5] = mn; s_mx[tid >> 5] = mx; }
    __syncthreads();                          // also covers s_tab
    if (tid < 32) {
        mn = (tid < 18) ? s_mn[tid] : 3.4e38f;
        mx = (tid < 18) ? s_mx[tid] : -3.4e38f;
#pragma unroll
        for (int o = 16; o > 0; o >>= 1) {
            mn = fminf(mn, __shfl_xor_sync(0xffffffffu, mn, o));
            mx = fmaxf(mx, __shfl_xor_sync(0xffffffffu, mx, o));
        }
        if (tid == 0) { s_stat[0] = mn; s_stat[1] = (mx - mn) + 1e-8f; }
    }
    __syncthreads();
    const float zmn   = s_stat[0];
    const float denom = s_stat[1];

    // ---- normalized z for this thread's 4 j's (same expr as reference) ----
    const float zjv[4] = { (d4.x - zmn) / denom, (d4.y - zmn) / denom,
                           (d4.z - zmn) / denom, (d4.w - zmn) / denom };

    const int cp  = tid & (NCOPY - 1);       // replication copy for this lane
    const int rj  = j0 / GW;
    const int cj0 = j0 - rj * GW;            // 4 j's share a pixel row
    const float XY_SCALE = 16.0f / 47.0f;
    const size_t plane = (size_t)NPIX * NPIX;

#pragma unroll 1
    for (int ii = 0; ii < NI; ++ii) {
        const int i  = i0 + ii;
        const int ri = i / GW;
        const int ci = i - ri * GW;
        const float zi = (__ldg(&depth[b * NPIX + i]) - zmn) / denom;

        float qy = rintf((float)(ri - rj) * XY_SCALE);
        qy = fminf(fmaxf(qy, -16.0f), 16.0f);
        const int iy = (int)qy + PATCH_NUM + RPE_NUM;

        int ixv[4], izv[4];
#pragma unroll
        for (int k = 0; k < 4; ++k) {
            float qx = rintf((float)(ci - (cj0 + k)) * XY_SCALE);
            qx = fminf(fmaxf(qx, -16.0f), 16.0f);
            ixv[k] = (int)qx + PATCH_NUM;

            float qz = rintf((zi - zjv[k]) * 16.0f);
            qz = fminf(fmaxf(qz, -16.0f), 16.0f);
            izv[k] = (int)qz + PATCH_NUM + 2 * RPE_NUM;
        }

        const size_t base = ((size_t)(b * NUM_HEADS) * NPIX + (size_t)i) * NPIX + j0;

        // half=0 -> heads 0..3, half=1 -> heads 4..7 (caps live registers)
#pragma unroll
        for (int half = 0; half < 2; ++half) {
            const uint2 tyu = s_tab[half][iy][cp];
            const float2 tya = __half22float2(*reinterpret_cast<const __half2*>(&tyu.x));
            const float2 tyb = __half22float2(*reinterpret_cast<const __half2*>(&tyu.y));

            float r0[4], r1[4], r2[4], r3[4];
#pragma unroll
            for (int k = 0; k < 4; ++k) {
                const uint2 txu = s_tab[half][ixv[k]][cp];
                const uint2 tzu = s_tab[half][izv[k]][cp];
                const float2 txa = __half22float2(*reinterpret_cast<const __half2*>(&txu.x));
                const float2 txb = __half22float2(*reinterpret_cast<const __half2*>(&txu.y));
                const float2 tza = __half22float2(*reinterpret_cast<const __half2*>(&tzu.x));
                const float2 tzb = __half22float2(*reinterpret_cast<const __half2*>(&tzu.y));
                // match reference sum order: (x + y) + z  (fp32 adds)
                r0[k] = (txa.x + tya.x) + tza.x;
                r1[k] = (txa.y + tya.y) + tza.y;
                r2[k] = (txb.x + tyb.x) + tzb.x;
                r3[k] = (txb.y + tyb.y) + tzb.y;
            }
            const size_t hb = base + (size_t)(half * 4) * plane;
            __stcs(reinterpret_cast<float4*>(out + hb + 0 * plane),
                   make_float4(r0[0], r0[1], r0[2], r0[3]));
            __stcs(reinterpret_cast<float4*>(out + hb + 1 * plane),
                   make_float4(r1[0], r1[1], r1[2], r1[3]));
            __stcs(reinterpret_cast<float4*>(out + hb + 2 * plane),
                   make_float4(r2[0], r2[1], r2[2], r2[3]));
            __stcs(reinterpret_cast<float4*>(out + hb + 3 * plane),
                   make_float4(r3[0], r3[1], r3[2], r3[3]));
        }
    }
}

// ---------------------------------------------------------------------------
extern "C" void kernel_launch(void* const* d_in, const int* in_sizes, int n_in,
                              void* d_out, int out_size) {
    const float*  depth = (const float*)d_in[0];     // (2,48,48) f32
    const float4* table = (const float4*)d_in[1];    // (99,8) f32 -> 198 float4
    float* out = (float*)d_out;                      // (2,8,2304,2304) f32

    dim3 grid(NPIX / NI, NB);
    rpe_kernel<<<grid, 576>>>(depth, table, out);
}

// round 10
// speedup vs baseline: 1.0706x; 1.0706x over previous
#include <cuda_runtime.h>
#include <cuda_fp16.h>

#define PATCH_NUM 16
#define RPE_NUM   33          // 2*PATCH_NUM + 1
#define NUM_HEADS 8
#define GH        48
#define GW        48
#define NPIX      2304        // 48*48
#define NB        2
#define TAB_ROWS  (3 * RPE_NUM)   // 99
#define NI        2               // query pixels per block
#define NCOPY     16              // smem replication copies

// Scratch for normalized depth (allocation-free: __device__ global).
__device__ __align__(16) float g_znorm[NB * NPIX];

// ---------------------------------------------------------------------------
// Kernel 1: per-image min/max + normalization. One block per image,
// 288 threads x 2 float4 loads each (2304 floats), float4 stores.
// ---------------------------------------------------------------------------
__global__ __launch_bounds__(288) void minmax_norm_kernel(
    const float* __restrict__ depth)
{
    const int b = blockIdx.x;
    const float4* d4p = reinterpret_cast<const float4*>(depth + b * NPIX);
    __shared__ float s_mn[9], s_mx[9];
    const int tid = threadIdx.x;   // 288 threads -> 9 warps

    const float4 a = d4p[tid];
    const float4 c = d4p[tid + 288];

    float mn = fminf(fminf(fminf(a.x, a.y), fminf(a.z, a.w)),
                     fminf(fminf(c.x, c.y), fminf(c.z, c.w)));
    float mx = fmaxf(fmaxf(fmaxf(a.x, a.y), fmaxf(a.z, a.w)),
                     fmaxf(fmaxf(c.x, c.y), fmaxf(c.z, c.w)));
#pragma unroll
    for (int o = 16; o > 0; o >>= 1) {
        mn = fminf(mn, __shfl_xor_sync(0xffffffffu, mn, o));
        mx = fmaxf(mx, __shfl_xor_sync(0xffffffffu, mx, o));
    }
    if ((tid & 31) == 0) { s_mn[tid >> 5] = mn; s_mx[tid >> 5] = mx; }
    __syncthreads();
    if (tid < 32) {
        mn = (tid < 9) ? s_mn[tid] : 3.4e38f;
        mx = (tid < 9) ? s_mx[tid] : -3.4e38f;
#pragma unroll
        for (int o = 8; o > 0; o >>= 1) {
            mn = fminf(mn, __shfl_xor_sync(0xffffffffu, mn, o));
            mx = fmaxf(mx, __shfl_xor_sync(0xffffffffu, mx, o));
        }
        if (tid == 0) { s_mn[0] = mn; s_mx[0] = (mx - mn) + 1e-8f; }
    }
    __syncthreads();
    const float zmn   = s_mn[0];
    const float denom = s_mx[0];

    float4* zp = reinterpret_cast<float4*>(g_znorm + b * NPIX);
    zp[tid] = make_float4((a.x - zmn) / denom, (a.y - zmn) / denom,
                          (a.z - zmn) / denom, (a.w - zmn) / denom);
    zp[tid + 288] = make_float4((c.x - zmn) / denom, (c.y - zmn) / denom,
                                (c.z - zmn) / denom, (c.w - zmn) / denom);
}

// ---------------------------------------------------------------------------
// Kernel 2: one block per (i-pair, b). 576 threads x 4 consecutive j each.
//
// Table in smem as fp16: each row-half = 4 halves = 8B (LDS.64), replicated
// 16x with 128B row stride. Lane uses copy = tid & 15, so within each
// 16-lane LDS.64 phase lanes hit 16 distinct 8B slots spanning all 32 banks
// -> every gather (incl. data-dependent z) is conflict-free at HALF the
// smem bytes of the fp32 layout. Converts to fp32 before adding (adds and
// association order match the reference; only table representation is fp16).
// ---------------------------------------------------------------------------
__global__ __launch_bounds__(576, 2) void rpe_kernel(
    const float4* __restrict__ table4, float* __restrict__ out)
{
    __shared__ __align__(128) uint2 s_tab[2][TAB_ROWS][NCOPY];  // 25344 B

    const int tid = threadIdx.x;
    const int i0  = blockIdx.x * NI;         // first query pixel of this block
    const int b   = blockIdx.y;              // batch

    // Prologue: convert table to fp16 and replicate (2 halves x 99 rows).
    for (int e = tid; e < 2 * TAB_ROWS; e += 576) {
        const int half = (e >= TAB_ROWS) ? 1 : 0;
        const int row  = e - half * TAB_ROWS;
        const float4 f = __ldg(&table4[row * 2 + half]);
        const __half2 a  = __floats2half2_rn(f.x, f.y);
        const __half2 bb = __floats2half2_rn(f.z, f.w);
        uint2 p;
        p.x = *reinterpret_cast<const unsigned int*>(&a);
        p.y = *reinterpret_cast<const unsigned int*>(&bb);
#pragma unroll
        for (int cpw = 0; cpw < NCOPY; ++cpw) s_tab[half][row][cpw] = p;
    }
    __syncthreads();

    const int cp = tid & (NCOPY - 1);        // replication copy for this lane

    const int j0  = tid * 4;                 // 576*4 == 2304 == NPIX
    const int rj  = j0 / GW;
    const int cj0 = j0 - rj * GW;            // 4 j's share a pixel row
    const float4 zj4 = *reinterpret_cast<const float4*>(&g_znorm[b * NPIX + j0]);
    const float zjv[4] = { zj4.x, zj4.y, zj4.z, zj4.w };

    const float XY_SCALE = 16.0f / 47.0f;
    const size_t plane = (size_t)NPIX * NPIX;

#pragma unroll 1
    for (int ii = 0; ii < NI; ++ii) {
        const int i  = i0 + ii;
        const int ri = i / GW;
        const int ci = i - ri * GW;
        const float zi = __ldg(&g_znorm[b * NPIX + i]);

        float qy = rintf((float)(ri - rj) * XY_SCALE);
        qy = fminf(fmaxf(qy, -16.0f), 16.0f);
        const int iy = (int)qy + PATCH_NUM + RPE_NUM;

        int ixv[4], izv[4];
#pragma unroll
        for (int k = 0; k < 4; ++k) {
            float qx = rintf((float)(ci - (cj0 + k)) * XY_SCALE);
            qx = fminf(fmaxf(qx, -16.0f), 16.0f);
            ixv[k] = (int)qx + PATCH_NUM;

            float qz = rintf((zi - zjv[k]) * 16.0f);
            qz = fminf(fmaxf(qz, -16.0f), 16.0f);
            izv[k] = (int)qz + PATCH_NUM + 2 * RPE_NUM;
        }

        const size_t base = ((size_t)(b * NUM_HEADS) * NPIX + (size_t)i) * NPIX + j0;

        // half=0 -> heads 0..3, half=1 -> heads 4..7 (caps live registers)
#pragma unroll
        for (int half = 0; half < 2; ++half) {
            const uint2 tyu = s_tab[half][iy][cp];
            const float2 tya = __half22float2(*reinterpret_cast<const __half2*>(&tyu.x));
            const float2 tyb = __half22float2(*reinterpret_cast<const __half2*>(&tyu.y));

            float r0[4], r1[4], r2[4], r3[4];
#pragma unroll
            for (int k = 0; k < 4; ++k) {
                const uint2 txu = s_tab[half][ixv[k]][cp];
                const uint2 tzu = s_tab[half][izv[k]][cp];
                const float2 txa = __half22float2(*reinterpret_cast<const __half2*>(&txu.x));
                const float2 txb = __half22float2(*reinterpret_cast<const __half2*>(&txu.y));
                const float2 tza = __half22float2(*reinterpret_cast<const __half2*>(&tzu.x));
                const float2 tzb = __half22float2(*reinterpret_cast<const __half2*>(&tzu.y));
                // match reference sum order: (x + y) + z  (fp32 adds)
                r0[k] = (txa.x + tya.x) + tza.x;
                r1[k] = (txa.y + tya.y) + tza.y;
                r2[k] = (txb.x + tyb.x) + tzb.x;
                r3[k] = (txb.y + tyb.y) + tzb.y;
            }
            const size_t hb = base + (size_t)(half * 4) * plane;
            __stcs(reinterpret_cast<float4*>(out + hb + 0 * plane),
                   make_float4(r0[0], r0[1], r0[2], r0[3]));
            __stcs(reinterpret_cast<float4*>(out + hb + 1 * plane),
                   make_float4(r1[0], r1[1], r1[2], r1[3]));
            __stcs(reinterpret_cast<float4*>(out + hb + 2 * plane),
                   make_float4(r2[0], r2[1], r2[2], r2[3]));
            __stcs(reinterpret_cast<float4*>(out + hb + 3 * plane),
                   make_float4(r3[0], r3[1], r3[2], r3[3]));
        }
    }
}

// ---------------------------------------------------------------------------
extern "C" void kernel_launch(void* const* d_in, const int* in_sizes, int n_in,
                              void* d_out, int out_size) {
    const float*  depth = (const float*)d_in[0];     // (2,48,48) f32
    const float4* table = (const float4*)d_in[1];    // (99,8) f32 -> 198 float4
    float* out = (float*)d_out;                      // (2,8,2304,2304) f32

    minmax_norm_kernel<<<NB, 288>>>(depth);

    dim3 grid(NPIX / NI, NB);
    rpe_kernel<<<grid, 576>>>(table, out);
}

// round 11
// speedup vs baseline: 1.0972x; 1.0249x over previous
#include <cuda_runtime.h>
#include <cuda_fp16.h>

#define PATCH_NUM 16
#define RPE_NUM   33          // 2*PATCH_NUM + 1
#define NUM_HEADS 8
#define GH        48
#define GW        48
#define NPIX      2304        // 48*48
#define NB        2
#define TAB_ROWS  (3 * RPE_NUM)   // 99
#define NI        4               // query pixels per block (one head-half)
#define NCOPY     16              // smem replication copies

// Scratch for normalized depth (allocation-free: __device__ global).
__device__ __align__(16) float g_znorm[NB * NPIX];

// ---------------------------------------------------------------------------
// Kernel 1: per-image min/max + normalization. One block per image,
// 288 threads x 2 float4 loads each (2304 floats), float4 stores.
// ---------------------------------------------------------------------------
__global__ __launch_bounds__(288) void minmax_norm_kernel(
    const float* __restrict__ depth)
{
    const int b = blockIdx.x;
    const float4* d4p = reinterpret_cast<const float4*>(depth + b * NPIX);
    __shared__ float s_mn[9], s_mx[9];
    const int tid = threadIdx.x;   // 288 threads -> 9 warps

    const float4 a = d4p[tid];
    const float4 c = d4p[tid + 288];

    float mn = fminf(fminf(fminf(a.x, a.y), fminf(a.z, a.w)),
                     fminf(fminf(c.x, c.y), fminf(c.z, c.w)));
    float mx = fmaxf(fmaxf(fmaxf(a.x, a.y), fmaxf(a.z, a.w)),
                     fmaxf(fmaxf(c.x, c.y), fmaxf(c.z, c.w)));
#pragma unroll
    for (int o = 16; o > 0; o >>= 1) {
        mn = fminf(mn, __shfl_xor_sync(0xffffffffu, mn, o));
        mx = fmaxf(mx, __shfl_xor_sync(0xffffffffu, mx, o));
    }
    if ((tid & 31) == 0) { s_mn[tid >> 5] = mn; s_mx[tid >> 5] = mx; }
    __syncthreads();
    if (tid < 32) {
        mn = (tid < 9) ? s_mn[tid] : 3.4e38f;
        mx = (tid < 9) ? s_mx[tid] : -3.4e38f;
#pragma unroll
        for (int o = 8; o > 0; o >>= 1) {
            mn = fminf(mn, __shfl_xor_sync(0xffffffffu, mn, o));
            mx = fmaxf(mx, __shfl_xor_sync(0xffffffffu, mx, o));
        }
        if (tid == 0) { s_mn[0] = mn; s_mx[0] = (mx - mn) + 1e-8f; }
    }
    __syncthreads();
    const float zmn   = s_mn[0];
    const float denom = s_mx[0];

    float4* zp = reinterpret_cast<float4*>(g_znorm + b * NPIX);
    zp[tid] = make_float4((a.x - zmn) / denom, (a.y - zmn) / denom,
                          (a.z - zmn) / denom, (a.w - zmn) / denom);
    zp[tid + 288] = make_float4((c.x - zmn) / denom, (c.y - zmn) / denom,
                                (c.z - zmn) / denom, (c.w - zmn) / denom);
}

// ---------------------------------------------------------------------------
// Kernel 2: one block per (i-quad, head-half, b). 576 threads x 4 j each,
// NI=4 query pixels, ONE table half (4 heads) per block.
//
// Per-thread gather/store totals identical to the (2 i x 8 heads) shape,
// but each block's writes form 4 planes x 4 consecutive i-rows = 36KB
// contiguous regions -> better DRAM write-drain locality.
//
// Table half in smem as fp16: row = 4 halves = 8B (LDS.64), replicated 16x
// with 128B row stride; copy = tid & 15 -> all gathers conflict-free.
// fp32 adds in reference association order; only table repr is fp16.
// ---------------------------------------------------------------------------
__global__ __launch_bounds__(576, 2) void rpe_kernel(
    const float4* __restrict__ table4, float* __restrict__ out)
{
    __shared__ __align__(128) uint2 s_tab[TAB_ROWS][NCOPY];   // 12672 B

    const int tid  = threadIdx.x;
    const int i0   = blockIdx.x * NI;        // first query pixel of this block
    const int half = blockIdx.y;             // table half: heads 4*half..4*half+3
    const int b    = blockIdx.z;             // batch

    // Prologue: convert this half's table rows to fp16 and replicate.
    for (int row = tid; row < TAB_ROWS; row += 576) {
        const float4 f = __ldg(&table4[row * 2 + half]);
        const __half2 a  = __floats2half2_rn(f.x, f.y);
        const __half2 bb = __floats2half2_rn(f.z, f.w);
        uint2 p;
        p.x = *reinterpret_cast<const unsigned int*>(&a);
        p.y = *reinterpret_cast<const unsigned int*>(&bb);
#pragma unroll
        for (int cpw = 0; cpw < NCOPY; ++cpw) s_tab[row][cpw] = p;
    }
    __syncthreads();

    const int cp = tid & (NCOPY - 1);        // replication copy for this lane

    const int j0  = tid * 4;                 // 576*4 == 2304 == NPIX
    const int rj  = j0 / GW;
    const int cj0 = j0 - rj * GW;            // 4 j's share a pixel row
    const float4 zj4 = *reinterpret_cast<const float4*>(&g_znorm[b * NPIX + j0]);
    const float zjv[4] = { zj4.x, zj4.y, zj4.z, zj4.w };

    const float XY_SCALE = 16.0f / 47.0f;
    const size_t plane = (size_t)NPIX * NPIX;

#pragma unroll 1
    for (int ii = 0; ii < NI; ++ii) {
        const int i  = i0 + ii;
        const int ri = i / GW;
        const int ci = i - ri * GW;
        const float zi = __ldg(&g_znorm[b * NPIX + i]);

        float qy = rintf((float)(ri - rj) * XY_SCALE);
        qy = fminf(fmaxf(qy, -16.0f), 16.0f);
        const int iy = (int)qy + PATCH_NUM + RPE_NUM;

        int ixv[4], izv[4];
#pragma unroll
        for (int k = 0; k < 4; ++k) {
            float qx = rintf((float)(ci - (cj0 + k)) * XY_SCALE);
            qx = fminf(fmaxf(qx, -16.0f), 16.0f);
            ixv[k] = (int)qx + PATCH_NUM;

            float qz = rintf((zi - zjv[k]) * 16.0f);
            qz = fminf(fmaxf(qz, -16.0f), 16.0f);
            izv[k] = (int)qz + PATCH_NUM + 2 * RPE_NUM;
        }

        const uint2 tyu = s_tab[iy][cp];
        const float2 tya = __half22float2(*reinterpret_cast<const __half2*>(&tyu.x));
        const float2 tyb = __half22float2(*reinterpret_cast<const __half2*>(&tyu.y));

        float r0[4], r1[4], r2[4], r3[4];
#pragma unroll
        for (int k = 0; k < 4; ++k) {
            const uint2 txu = s_tab[ixv[k]][cp];
            const uint2 tzu = s_tab[izv[k]][cp];
            const float2 txa = __half22float2(*reinterpret_cast<const __half2*>(&txu.x));
            const float2 txb = __half22float2(*reinterpret_cast<const __half2*>(&txu.y));
            const float2 tza = __half22float2(*reinterpret_cast<const __half2*>(&tzu.x));
            const float2 tzb = __half22float2(*reinterpret_cast<const __half2*>(&tzu.y));
            // match reference sum order: (x + y) + z  (fp32 adds)
            r0[k] = (txa.x + tya.x) + tza.x;
            r1[k] = (txa.y + tya.y) + tza.y;
            r2[k] = (txb.x + tyb.x) + tzb.x;
            r3[k] = (txb.y + tyb.y) + tzb.y;
        }

        const size_t base = ((size_t)(b * NUM_HEADS + half * 4) * NPIX + (size_t)i) * NPIX + j0;
        __stcs(reinterpret_cast<float4*>(out + base + 0 * plane),
               make_float4(r0[0], r0[1], r0[2], r0[3]));
        __stcs(reinterpret_cast<float4*>(out + base + 1 * plane),
               make_float4(r1[0], r1[1], r1[2], r1[3]));
        __stcs(reinterpret_cast<float4*>(out + base + 2 * plane),
               make_float4(r2[0], r2[1], r2[2], r2[3]));
        __stcs(reinterpret_cast<float4*>(out + base + 3 * plane),
               make_float4(r3[0], r3[1], r3[2], r3[3]));
    }
}

// ---------------------------------------------------------------------------
extern "C" void kernel_launch(void* const* d_in, const int* in_sizes, int n_in,
                              void* d_out, int out_size) {
    const float*  depth = (const float*)d_in[0];     // (2,48,48) f32
    const float4* table = (const float4*)d_in[1];    // (99,8) f32 -> 198 float4
    float* out = (float*)d_out;                      // (2,8,2304,2304) f32

    minmax_norm_kernel<<<NB, 288>>>(depth);

    dim3 grid(NPIX / NI, 2, NB);
    rpe_kernel<<<grid, 576>>>(table, out);
}